// round 7
// baseline (speedup 1.0000x reference)
#include <cuda_runtime.h>
#include <cuda_bf16.h>
#include <cstdint>

// token_reprs: [B=32, L=512, H=768] f32 ; pos_idx: [B,E=32,M=8,S=4] i32
// out f32: entity [B,E,H] @0 ; mentions [B,E,M,H] @786432 ; mask [B,E,M] @7077888

#define B_ 32
#define L_ 512
#define H_ 768
#define E_ 32
#define M_ 8
#define S_ 4
#define HV (H_ / 4)          // 192 float4 per row
#define CHUNK 32             // float4 columns per block
#define NCHUNK (HV / CHUNK)  // 6
#define IDX_PER_B (E_ * M_ * S_)   // 1024

// Block = (batch, H-chunk). 256 threads: warp w = mention w, lane = column.
// All 32 entities of the batch processed by one block -> duplicate gathered
// rows (E[dup] = 57% of 1024 draws over 512 rows) hit L1 instead of L2,
// cutting LTS traffic ~96 MB -> ~41 MB of reads.
__global__ __launch_bounds__(256, 2)
void entity_repr_kernel(const float* __restrict__ tok,
                        const int* __restrict__ pos,
                        float* __restrict__ ent,
                        float* __restrict__ men,
                        float* __restrict__ mask)
{
    __shared__ float4 smen[2][M_][CHUNK];   // parity-buffered mention stash
    __shared__ int sidx[IDX_PER_B];

    const int bx   = blockIdx.x;
    const int b    = bx & (B_ - 1);     // batch (chunk-major grid)
    const int c    = bx >> 5;           // chunk 0..5
    const int t    = threadIdx.x;
    const int w    = t >> 5;            // warp = mention
    const int lane = t & 31;            // column within chunk

    for (int i = t; i < IDX_PER_B; i += 256)
        sidx[i] = pos[(size_t)b * IDX_PER_B + i];
    __syncthreads();

    // thread-local base: row r of this batch, this chunk, this column
    const float4* __restrict__ tokb =
        reinterpret_cast<const float4*>(tok)
        + (size_t)b * L_ * HV + c * CHUNK + lane;

    float4* __restrict__ men4 =
        reinterpret_cast<float4*>(men)
        + (size_t)b * E_ * M_ * HV + c * CHUNK + lane;
    float4* __restrict__ ent4 =
        reinterpret_cast<float4*>(ent)
        + (size_t)b * E_ * HV + c * CHUNK + lane;

    // Prefetch entity 0 (mention w)
    float4 a0, a1, a2, a3;
    {
        const int* I = sidx + w * S_;
        a0 = __ldg(&tokb[(size_t)I[0] * HV]);
        a1 = __ldg(&tokb[(size_t)I[1] * HV]);
        a2 = __ldg(&tokb[(size_t)I[2] * HV]);
        a3 = __ldg(&tokb[(size_t)I[3] * HV]);
    }

    for (int e = 0; e < E_; e++) {
        // Prefetch entity e+1 BEFORE the barrier: gathers stay in flight
        // across the sync, hiding L1/L2 latency behind the reduce+store.
        float4 b0 = a0, b1 = a1, b2 = a2, b3 = a3;
        if (e + 1 < E_) {
            const int* I = sidx + (e + 1) * (M_ * S_) + w * S_;
            b0 = __ldg(&tokb[(size_t)I[0] * HV]);
            b1 = __ldg(&tokb[(size_t)I[1] * HV]);
            b2 = __ldg(&tokb[(size_t)I[2] * HV]);
            b3 = __ldg(&tokb[(size_t)I[3] * HV]);
        }

        float4 r;
        r.x = (a0.x + a1.x + a2.x + a3.x) * 0.25f;
        r.y = (a0.y + a1.y + a2.y + a3.y) * 0.25f;
        r.z = (a0.z + a1.z + a2.z + a3.z) * 0.25f;
        r.w = (a0.w + a1.w + a2.w + a3.w) * 0.25f;

        men4[((size_t)e * M_ + w) * HV] = r;
        smen[e & 1][w][lane] = r;
        __syncthreads();

        // Rotating warp reduces entity e from the parity stash.
        // Safe: these slots are rewritten at entity e+2, behind another BAR.
        if (w == (e & 7)) {
            const float4 s0 = smen[e & 1][0][lane];
            const float4 s1 = smen[e & 1][1][lane];
            const float4 s2 = smen[e & 1][2][lane];
            const float4 s3 = smen[e & 1][3][lane];
            const float4 s4 = smen[e & 1][4][lane];
            const float4 s5 = smen[e & 1][5][lane];
            const float4 s6 = smen[e & 1][6][lane];
            const float4 s7 = smen[e & 1][7][lane];
            float4 es;
            es.x = (s0.x+s1.x+s2.x+s3.x+s4.x+s5.x+s6.x+s7.x) * 0.125f;
            es.y = (s0.y+s1.y+s2.y+s3.y+s4.y+s5.y+s6.y+s7.y) * 0.125f;
            es.z = (s0.z+s1.z+s2.z+s3.z+s4.z+s5.z+s6.z+s7.z) * 0.125f;
            es.w = (s0.w+s1.w+s2.w+s3.w+s4.w+s5.w+s6.w+s7.w) * 0.125f;
            ent4[(size_t)e * HV] = es;
        }

        a0 = b0; a1 = b1; a2 = b2; a3 = b3;
    }

    if (c == 0) {
        // mask [E, M] for this batch: exactly 256 values
        mask[(size_t)b * (E_ * M_) + t] = 1.0f;
    }
}

extern "C" void kernel_launch(void* const* d_in, const int* in_sizes, int n_in,
                              void* d_out, int out_size)
{
    const float* tok = (const float*)d_in[0];
    const int*   pos = (const int*)d_in[1];

    float* out = (float*)d_out;
    float* ent  = out;                                  // 786432
    float* men  = out + (size_t)B_ * E_ * H_;           // +786432
    float* mask = men + (size_t)B_ * E_ * M_ * H_;      // +6291456

    static int configured = 0;
    if (!configured) {
        // Maximize L1D so the ~227 KB per-block row working set stays resident.
        cudaFuncSetAttribute(entity_repr_kernel,
                             cudaFuncAttributePreferredSharedMemoryCarveout,
                             cudaSharedmemCarveoutMaxL1);
        configured = 1;
    }

    entity_repr_kernel<<<B_ * NCHUNK, 256>>>(tok, pos, ent, men, mask);
}

// round 8
// speedup vs baseline: 1.8291x; 1.8291x over previous
#include <cuda_runtime.h>
#include <cuda_bf16.h>
#include <cstdint>

// token_reprs: [B=32, L=512, H=768] f32 ; pos_idx: [B,E=32,M=8,S=4] i32
// out f32: entity [B,E,H] @0 ; mentions [B,E,M,H] @786432 ; mask [B,E,M] @7077888

#define B_ 32
#define L_ 512
#define H_ 768
#define E_ 32
#define M_ 8
#define S_ 4
#define HV (H_ / 4)          // 192 float4 per row

// R2 structure (best so far) + forced 10 blocks/SM (32-reg budget) for
// 60 resident warps/SM instead of 48: more in-flight gather bytes chip-wide.
__global__ __launch_bounds__(HV, 10)
void entity_repr_kernel(const float* __restrict__ tok,
                        const int* __restrict__ pos,
                        float* __restrict__ ent,
                        float* __restrict__ men,
                        float* __restrict__ mask)
{
    const int be = blockIdx.x;          // 0 .. B*E-1
    const int b  = be >> 5;             // E_ == 32

    __shared__ int sidx[M_ * S_];
    if (threadIdx.x < M_ * S_) {
        sidx[threadIdx.x] = pos[(size_t)be * (M_ * S_) + threadIdx.x];
    }
    __syncthreads();

    const int t = threadIdx.x;          // float4 column index, 0..191
    const float4* __restrict__ tokb =
        reinterpret_cast<const float4*>(tok) + (size_t)b * L_ * HV;

    float4* __restrict__ men4 =
        reinterpret_cast<float4*>(men) + ((size_t)be * M_) * HV;
    float4* __restrict__ ent4 =
        reinterpret_cast<float4*>(ent) + (size_t)be * HV;

    float ex = 0.f, ey = 0.f, ez = 0.f, ew = 0.f;

    #pragma unroll
    for (int m = 0; m < M_; m++) {
        // 4 independent gathered loads per mention (each row 3KB contiguous,
        // warp reads 512B fully coalesced)
        const float4 v0 = tokb[(size_t)sidx[m * S_ + 0] * HV + t];
        const float4 v1 = tokb[(size_t)sidx[m * S_ + 1] * HV + t];
        const float4 v2 = tokb[(size_t)sidx[m * S_ + 2] * HV + t];
        const float4 v3 = tokb[(size_t)sidx[m * S_ + 3] * HV + t];

        float4 r;
        r.x = (v0.x + v1.x + v2.x + v3.x) * 0.25f;
        r.y = (v0.y + v1.y + v2.y + v3.y) * 0.25f;
        r.z = (v0.z + v1.z + v2.z + v3.z) * 0.25f;
        r.w = (v0.w + v1.w + v2.w + v3.w) * 0.25f;

        men4[(size_t)m * HV + t] = r;

        ex += r.x; ey += r.y; ez += r.z; ew += r.w;
    }

    float4 er;
    er.x = ex * 0.125f; er.y = ey * 0.125f;
    er.z = ez * 0.125f; er.w = ew * 0.125f;
    ent4[t] = er;

    if (t < M_) {
        mask[(size_t)be * M_ + t] = 1.0f;
    }
}

extern "C" void kernel_launch(void* const* d_in, const int* in_sizes, int n_in,
                              void* d_out, int out_size)
{
    const float* tok = (const float*)d_in[0];
    const int*   pos = (const int*)d_in[1];

    float* out = (float*)d_out;
    float* ent  = out;                                  // 786432
    float* men  = out + (size_t)B_ * E_ * H_;           // +786432
    float* mask = men + (size_t)B_ * E_ * M_ * H_;      // +6291456

    entity_repr_kernel<<<B_ * E_, HV>>>(tok, pos, ent, men, mask);
}